// round 16
// baseline (speedup 1.0000x reference)
#include <cuda_runtime.h>
#include <cuda_fp16.h>
#include <math.h>
#include <stdint.h>

// ---------------- Problem constants ----------------
#define T_TOK  8192
#define DM     1024
#define DFF    2048
#define NE     16
#define TOPK   2
#define CAP    1280
#define EC     (NE*CAP)

// ---------------- Scratch (device globals; no allocations) ----------------
__device__ int   g_sel [T_TOK*TOPK];
__device__ float g_wt  [T_TOK*TOPK];
__device__ int   g_slot[T_TOK*TOPK];
__device__ int   g_src [EC];
__device__ int   g_filled[NE];
__device__ __half g_Xh [(size_t)EC*DM];
__device__ __half g_Hh [(size_t)EC*DFF];
__device__ __half g_W1h[(size_t)NE*DFF*DM];   // [E][N=DFF][K=DM] (K-major)
__device__ __half g_W2h[(size_t)NE*DM*DFF];   // [E][N=DM][K=DFF]
__device__ __half g_Yh[(size_t)EC*DM];

// ---------------- PTX helpers (baseline ISA only) ----------------
__device__ __forceinline__ uint32_t smem_u32(const void* p) {
    uint32_t a;
    asm("{ .reg .u64 t; cvta.to.shared.u64 t, %1; cvt.u32.u64 %0, t; }" : "=r"(a) : "l"(p));
    return a;
}
__device__ __forceinline__ void cp16(uint32_t dst, const void* src) {
    asm volatile("cp.async.cg.shared.global [%0], [%1], 16;" :: "r"(dst), "l"(src));
}
#define CP_COMMIT() asm volatile("cp.async.commit_group;" ::: "memory")
template <int N>
__device__ __forceinline__ void cp_wait() {
    asm volatile("cp.async.wait_group %0;" :: "n"(N) : "memory");
}
__device__ __forceinline__ void ldsm4(uint32_t* r, uint32_t addr) {
    asm volatile("ldmatrix.sync.aligned.m8n8.x4.shared.b16 {%0,%1,%2,%3}, [%4];"
        : "=r"(r[0]), "=r"(r[1]), "=r"(r[2]), "=r"(r[3]) : "r"(addr));
}
// fp16-accumulate MMA, C = 0 (chain start)
__device__ __forceinline__ void mma16816_h0(uint32_t* d, const uint32_t* a, uint32_t b0, uint32_t b1) {
    asm volatile("mma.sync.aligned.m16n8k16.row.col.f16.f16.f16.f16 "
        "{%0,%1}, {%2,%3,%4,%5}, {%6,%7}, {%8,%9};"
        : "=r"(d[0]), "=r"(d[1])
        : "r"(a[0]), "r"(a[1]), "r"(a[2]), "r"(a[3]), "r"(b0), "r"(b1), "r"(0u), "r"(0u));
}
// fp16-accumulate MMA, chained (C = D)
__device__ __forceinline__ void mma16816_hc(uint32_t* d, const uint32_t* a, uint32_t b0, uint32_t b1) {
    asm volatile("mma.sync.aligned.m16n8k16.row.col.f16.f16.f16.f16 "
        "{%0,%1}, {%2,%3,%4,%5}, {%6,%7}, {%0,%1};"
        : "+r"(d[0]), "+r"(d[1])
        : "r"(a[0]), "r"(a[1]), "r"(a[2]), "r"(a[3]), "r"(b0), "r"(b1));
}
__device__ __forceinline__ float gelu_f(float x) {
    return 0.5f * x * (1.0f + erff(x * 0.70710678118654752440f));
}

// ---------------- 1) Gate ----------------
__global__ void gate_kernel(const float* __restrict__ x, const float* __restrict__ gw) {
    const int warp = threadIdx.x >> 5, lane = threadIdx.x & 31;
    const int t = blockIdx.x * 8 + warp;
    const float* xr = x + (size_t)t * DM;
    float xv[32];
#pragma unroll
    for (int j = 0; j < 32; j++) xv[j] = xr[lane + 32 * j];
    float logits[NE];
#pragma unroll
    for (int e = 0; e < NE; e++) {
        const float* g = gw + e * DM;
        float s = 0.f;
#pragma unroll
        for (int j = 0; j < 32; j++) s += xv[j] * g[lane + 32 * j];
#pragma unroll
        for (int o = 16; o > 0; o >>= 1) s += __shfl_xor_sync(0xffffffffu, s, o);
        logits[e] = s;
    }
    if (lane == 0) {
        float v0 = -1e30f, v1 = -1e30f; int i0 = 0, i1 = 0;
#pragma unroll
        for (int e = 0; e < NE; e++) {
            float p = 1.0f / (1.0f + expf(-logits[e]));
            if (p > v0)      { v1 = v0; i1 = i0; v0 = p; i0 = e; }
            else if (p > v1) { v1 = p;  i1 = e; }
        }
        float s = v0 + v1 + 1e-6f;
        g_sel[2*t] = i0; g_sel[2*t+1] = i1;
        g_wt [2*t] = v0 / s; g_wt [2*t+1] = v1 / s;
    }
}

// ---------------- 2) Ordered capacity ranking ----------------
__global__ void rank_kernel() {
    const int e = blockIdx.x, tid = threadIdx.x;
    const int ITEMS = (T_TOK * TOPK) / 256;
    const int base = tid * ITEMS;
    int cnt = 0;
    for (int i = 0; i < ITEMS; i++) cnt += (g_sel[base + i] == e);
    __shared__ int s[256];
    s[tid] = cnt;
    __syncthreads();
    int off = 0, tot = 0;
    for (int j = 0; j < 256; j++) { int v = s[j]; tot += v; if (j < tid) off += v; }
    int r = off;
    for (int i = 0; i < ITEMS; i++) {
        int idx = base + i;
        if (g_sel[idx] == e) {
            if (r < CAP) { g_slot[idx] = e * CAP + r; g_src[e * CAP + r] = idx; }
            else g_slot[idx] = -1;
            r++;
        }
    }
    int filled = tot < CAP ? tot : CAP;
    if (tid == 0) g_filled[e] = filled;
    for (int r2 = filled + tid; r2 < CAP; r2 += 256) g_src[e * CAP + r2] = -1;
}

// ---------------- 3) Fused prep: gather X->fp16  +  transpose/convert W1,W2 ----------------
#define NT1 32768   // (DFF/32)*(DM/32)*NE
__global__ void prep_kernel(const float* __restrict__ x,
                            const float* __restrict__ w1,
                            const float* __restrict__ w2) {
    const int tx = threadIdx.x, ty = threadIdx.y;
    const int tid = ty * 32 + tx;
    int b = blockIdx.x;

    if (b < EC) {                       // ---- gather + fp16 ----
        const int e = b / CAP;
        const int r = b - e * CAP;
        const int lim = (g_filled[e] + 127) & ~127;   // last computed tile boundary
        if (r >= lim) return;                         // rows never read by any GEMM tile
        const int src = g_src[b];
        __half2* dst = (__half2*)(g_Xh + (size_t)b * DM);
        if (src >= 0) {
            const float2* s = (const float2*)(x + (size_t)(src >> 1) * DM);
#pragma unroll
            for (int i = 0; i < 2; i++) {
                float2 v = s[tid + 256 * i];
                dst[tid + 256 * i] = __halves2half2(__float2half_rn(v.x), __float2half_rn(v.y));
            }
        } else {
            __half2 z = __halves2half2(__float2half_rn(0.f), __float2half_rn(0.f));
#pragma unroll
            for (int i = 0; i < 2; i++) dst[tid + 256 * i] = z;
        }
        return;
    }
    b -= EC;
    const int wsel = b >> 15;           // 0: W1, 1: W2
    const int r = b & (NT1 - 1);
    const int R = wsel ? DFF : DM;
    const int C = wsel ? DM : DFF;
    const float* s = (wsel ? w2 : w1);
    __half* dst = (wsel ? g_W2h : g_W1h);
    const int ctiles = C / 32;
    const int cx = r % ctiles;
    const int ry = (r / ctiles) % (R / 32);
    const int e  = r / (ctiles * (R / 32));
    const int c0 = cx * 32, r0 = ry * 32;
    s   += (size_t)e * R * C;
    dst += (size_t)e * R * C;

    __shared__ float t[32][33];
#pragma unroll
    for (int i = 0; i < 4; i++)
        t[ty + 8*i][tx] = s[(size_t)(r0 + ty + 8*i) * C + c0 + tx];
    __syncthreads();
#pragma unroll
    for (int it = 0; it < 2; it++) {
        const int idx = tid + 256 * it;
        const int oc_l = idx >> 4;
        const int p    = idx & 15;
        float v0 = t[2*p][oc_l], v1 = t[2*p + 1][oc_l];
        size_t o = (size_t)(c0 + oc_l) * R + r0 + 2 * p;
        *(__half2*)(dst + o) = __halves2half2(__float2half_rn(v0), __float2half_rn(v1));
    }
}

// ---------------- 4/5) single-pass fp16 HMMA GEMM, fp16-accum chunk chains ----------------
// CTA tile 128x128, K-chunk 32, 256 thr, warps 4(M)x2(N), warp tile 32x64.
// Per chunk: each m16n8 tile chains its 2 MMAs in fp16 accum, then promotes
// once into fp32. 64B rows + XOR swizzle; 6-stage ring, ONE barrier per
// chunk-pair; 2 CTAs/SM (96KB each).
#define TILE_SM  (128 * 64)           // 8192 B
#define STAGE_SM (2 * TILE_SM)        // 16384 B
#define NSTAGE   6
#define SMEMD    (NSTAGE * STAGE_SM)  // 98304 B

template <int KD, int ND, int PHASE>
__global__ __launch_bounds__(256, 2) void mma_gemm_kernel() {
    const int e  = blockIdx.z;
    const int m0 = blockIdx.y * 128;
    if (m0 >= g_filled[e]) return;     // padding tile: outputs never read

    extern __shared__ __align__(128) char dsm[];
    const uint32_t smem0 = smem_u32(dsm);

    const int n0 = blockIdx.x * 128;
    const int tid = threadIdx.x;
    const int lane = tid & 31, wid = tid >> 5;
    const int wm = wid & 3, wn = wid >> 2;     // warp -> (row 32*wm, col 64*wn)

    const char* A = (const char*)((PHASE == 0 ? g_Xh : g_Hh) + ((size_t)e * CAP + m0) * KD);
    const char* B = (const char*)((PHASE == 0 ? g_W1h : g_W2h) + ((size_t)e * ND + n0) * KD);

    float acc[2][8][4];
#pragma unroll
    for (int a = 0; a < 2; a++)
#pragma unroll
        for (int b = 0; b < 8; b++)
#pragma unroll
            for (int q = 0; q < 4; q++) acc[a][b][q] = 0.f;

    // ---- loader: rolling pointers, +64B per chunk ----
    const int lrow0 = tid >> 2, lseg = tid & 3;
    const uint32_t swzseg = (uint32_t)(lseg ^ ((lrow0 >> 1) & 3)) * 16;
    const uint32_t dA0 = lrow0 * 64 + swzseg;
    const char* pA0 = A + (size_t)lrow0 * (KD * 2) + lseg * 16;
    const char* pA1 = pA0 + (size_t)64 * (KD * 2);
    const char* pB0 = B + (size_t)lrow0 * (KD * 2) + lseg * 16;
    const char* pB1 = pB0 + (size_t)64 * (KD * 2);

    auto load_next = [&](int slot) {
        const uint32_t buf = smem0 + slot * STAGE_SM;
        cp16(buf + dA0,                   pA0);
        cp16(buf + dA0 + 64 * 64,         pA1);
        cp16(buf + TILE_SM + dA0,         pB0);
        cp16(buf + TILE_SM + dA0 + 64*64, pB1);
        CP_COMMIT();
        pA0 += 64; pA1 += 64; pB0 += 64; pB1 += 64;
    };

    const int NC = KD / 32;
    load_next(0); load_next(1); load_next(2); load_next(3);

    // ---- ldmatrix addressing (swizzled) ----
    const int lrow = lane & 15;
    const int hi   = (lane >> 4) & 1;
    const uint32_t swz = ((uint32_t)lrow >> 1) & 3;
    uint32_t offA[2], offB[4];
#pragma unroll
    for (int mt = 0; mt < 2; mt++) offA[mt] = (wm * 32 + mt * 16 + lrow) * 64;
#pragma unroll
    for (int g = 0; g < 4; g++)    offB[g] = (wn * 64 + g * 16 + lrow) * 64;
    uint32_t cb[2];
#pragma unroll
    for (int kk = 0; kk < 2; kk++) cb[kk] = (uint32_t)((2 * kk + hi) ^ swz) * 16;

    // fp16-accum chains: per m16n8 tile, 2 chained fp16 MMAs then one promote.
    auto compute_chunk = [&](int slot) {
        const uint32_t sA = smem0 + slot * STAGE_SM;
        const uint32_t sB = sA + TILE_SM;
        uint32_t ah0[2][4], ah1[2][4];
#pragma unroll
        for (int mt = 0; mt < 2; mt++) {
            ldsm4(ah0[mt], sA + offA[mt] + cb[0]);
            ldsm4(ah1[mt], sA + offA[mt] + cb[1]);
        }
#pragma unroll
        for (int g = 0; g < 4; g++) {
            uint32_t b0h[4], b1h[4];
            ldsm4(b0h, sB + offB[g] + cb[0]);
            ldsm4(b1h, sB + offB[g] + cb[1]);
#pragma unroll
            for (int mt = 0; mt < 2; mt++) {
#pragma unroll
                for (int half = 0; half < 2; half++) {
                    uint32_t d[2];
                    mma16816_h0(d, ah0[mt], b0h[half], b0h[half + 2]);
                    mma16816_hc(d, ah1[mt], b1h[half], b1h[half + 2]);
                    float* ac = acc[mt][2 * g + half];
                    float2 f0 = __half22float2(*reinterpret_cast<__half2*>(&d[0]));
                    float2 f1 = __half22float2(*reinterpret_cast<__half2*>(&d[1]));
                    ac[0] += f0.x; ac[1] += f0.y;
                    ac[2] += f1.x; ac[3] += f1.y;
                }
            }
        }
    };

    int sc = 0;       // slot of chunk p
    int sl = 4;       // slot of next chunk to load
    for (int p = 0; p < NC; p += 2) {
        if (p < NC - 2) cp_wait<2>(); else cp_wait<0>();
        __syncthreads();

        compute_chunk(sc);
        if (p + 4 < NC) load_next(sl);
        int sl2 = (sl + 1 == NSTAGE) ? 0 : sl + 1;
        if (p + 5 < NC) load_next(sl2);
        sl = (sl2 + 1 == NSTAGE) ? 0 : sl2 + 1;

        int sc2 = (sc + 1 == NSTAGE) ? 0 : sc + 1;
        compute_chunk(sc2);
        sc = (sc2 + 1 == NSTAGE) ? 0 : sc2 + 1;
    }

    // -------- epilogue (fp16 out; gelu on phase 0) --------
#pragma unroll
    for (int mt = 0; mt < 2; mt++) {
#pragma unroll
        for (int h = 0; h < 2; h++) {
            const int row = m0 + wm * 32 + mt * 16 + (lane >> 2) + 8 * h;
            const int colb = n0 + wn * 64 + 2 * (lane & 3);
            __half2* hp = (__half2*)((PHASE == 0 ? g_Hh : g_Yh) + ((size_t)e * CAP + row) * ND + colb);
#pragma unroll
            for (int nt = 0; nt < 8; nt++) {
                float v0 = acc[mt][nt][2*h];
                float v1 = acc[mt][nt][2*h + 1];
                if (PHASE == 0) { v0 = gelu_f(v0); v1 = gelu_f(v1); }
                hp[nt * 4] = __halves2half2(__float2half_rn(v0), __float2half_rn(v1));
            }
        }
    }
}

// ---------------- 6) Combine ----------------
__global__ void combine_kernel(float* __restrict__ out) {
    const int t = blockIdx.x;
    const int s0 = g_slot[2*t], s1 = g_slot[2*t+1];
    const float w0 = g_wt[2*t], w1 = g_wt[2*t+1];
    const __half2* Y2 = (const __half2*)g_Yh;
    float2* o = ((float2*)out) + (size_t)t * (DM / 2);
    for (int i = threadIdx.x; i < DM / 2; i += blockDim.x) {
        float2 r = make_float2(0.f, 0.f);
        if (s0 >= 0) {
            float2 y = __half22float2(Y2[(size_t)s0 * (DM/2) + i]);
            r.x += w0 * y.x; r.y += w0 * y.y;
        }
        if (s1 >= 0) {
            float2 y = __half22float2(Y2[(size_t)s1 * (DM/2) + i]);
            r.x += w1 * y.x; r.y += w1 * y.y;
        }
        o[i] = r;
    }
}

// ---------------- Launch ----------------
extern "C" void kernel_launch(void* const* d_in, const int* in_sizes, int n_in,
                              void* d_out, int out_size) {
    (void)in_sizes; (void)n_in; (void)out_size;
    const float* x  = (const float*)d_in[0];
    const float* gw = (const float*)d_in[1];
    const float* w1 = (const float*)d_in[2];   // [16,1024,2048]
    const float* w2 = (const float*)d_in[3];   // [16,2048,1024]
    float* out = (float*)d_out;

    cudaFuncSetAttribute(mma_gemm_kernel<DM,  DFF, 0>, cudaFuncAttributeMaxDynamicSharedMemorySize, SMEMD);
    cudaFuncSetAttribute(mma_gemm_kernel<DFF, DM,  1>, cudaFuncAttributeMaxDynamicSharedMemorySize, SMEMD);

    gate_kernel<<<T_TOK / 8, 256>>>(x, gw);
    rank_kernel<<<NE, 256>>>();
    prep_kernel<<<EC + 2 * NT1, dim3(32, 8)>>>(x, w1, w2);
    mma_gemm_kernel<DM,  DFF, 0><<<dim3(DFF/128, CAP/128, NE), 256, SMEMD>>>();
    mma_gemm_kernel<DFF, DM,  1><<<dim3(DM/128,  CAP/128, NE), 256, SMEMD>>>();
    combine_kernel<<<T_TOK, 256>>>(out);
}

// round 17
// speedup vs baseline: 1.2149x; 1.2149x over previous
#include <cuda_runtime.h>
#include <cuda_fp16.h>
#include <math.h>
#include <stdint.h>

// ---------------- Problem constants ----------------
#define T_TOK  8192
#define DM     1024
#define DFF    2048
#define NE     16
#define TOPK   2
#define CAP    1280
#define EC     (NE*CAP)

// ---------------- Scratch (device globals; no allocations) ----------------
__device__ int   g_sel [T_TOK*TOPK];
__device__ float g_wt  [T_TOK*TOPK];
__device__ int   g_slot[T_TOK*TOPK];
__device__ int   g_src [EC];
__device__ int   g_filled[NE];
__device__ __half g_Xt [(size_t)T_TOK*DM];    // token-indexed fp16 X (no padding copy)
__device__ __half g_Hh [(size_t)EC*DFF];
__device__ __half g_W1h[(size_t)NE*DFF*DM];   // [E][N=DFF][K=DM] (K-major)
__device__ __half g_W2h[(size_t)NE*DM*DFF];   // [E][N=DM][K=DFF]
__device__ __half g_Yh[(size_t)EC*DM];

// ---------------- PTX helpers (baseline ISA only) ----------------
__device__ __forceinline__ uint32_t smem_u32(const void* p) {
    uint32_t a;
    asm("{ .reg .u64 t; cvta.to.shared.u64 t, %1; cvt.u32.u64 %0, t; }" : "=r"(a) : "l"(p));
    return a;
}
__device__ __forceinline__ void cp16(uint32_t dst, const void* src) {
    asm volatile("cp.async.cg.shared.global [%0], [%1], 16;" :: "r"(dst), "l"(src));
}
#define CP_COMMIT() asm volatile("cp.async.commit_group;" ::: "memory")
template <int N>
__device__ __forceinline__ void cp_wait() {
    asm volatile("cp.async.wait_group %0;" :: "n"(N) : "memory");
}
__device__ __forceinline__ void ldsm4(uint32_t* r, uint32_t addr) {
    asm volatile("ldmatrix.sync.aligned.m8n8.x4.shared.b16 {%0,%1,%2,%3}, [%4];"
        : "=r"(r[0]), "=r"(r[1]), "=r"(r[2]), "=r"(r[3]) : "r"(addr));
}
__device__ __forceinline__ void mma16816(float* c, const uint32_t* a, uint32_t b0, uint32_t b1) {
    asm volatile("mma.sync.aligned.m16n8k16.row.col.f32.f16.f16.f32 "
        "{%0,%1,%2,%3}, {%4,%5,%6,%7}, {%8,%9}, {%0,%1,%2,%3};"
        : "+f"(c[0]), "+f"(c[1]), "+f"(c[2]), "+f"(c[3])
        : "r"(a[0]), "r"(a[1]), "r"(a[2]), "r"(a[3]), "r"(b0), "r"(b1));
}
__device__ __forceinline__ float gelu_f(float x) {
    return 0.5f * x * (1.0f + erff(x * 0.70710678118654752440f));
}

// ---------------- 1) Gate ----------------
__global__ void gate_kernel(const float* __restrict__ x, const float* __restrict__ gw) {
    const int warp = threadIdx.x >> 5, lane = threadIdx.x & 31;
    const int t = blockIdx.x * 8 + warp;
    const float* xr = x + (size_t)t * DM;
    float xv[32];
#pragma unroll
    for (int j = 0; j < 32; j++) xv[j] = xr[lane + 32 * j];
    float logits[NE];
#pragma unroll
    for (int e = 0; e < NE; e++) {
        const float* g = gw + e * DM;
        float s = 0.f;
#pragma unroll
        for (int j = 0; j < 32; j++) s += xv[j] * g[lane + 32 * j];
#pragma unroll
        for (int o = 16; o > 0; o >>= 1) s += __shfl_xor_sync(0xffffffffu, s, o);
        logits[e] = s;
    }
    if (lane == 0) {
        float v0 = -1e30f, v1 = -1e30f; int i0 = 0, i1 = 0;
#pragma unroll
        for (int e = 0; e < NE; e++) {
            float p = 1.0f / (1.0f + expf(-logits[e]));
            if (p > v0)      { v1 = v0; i1 = i0; v0 = p; i0 = e; }
            else if (p > v1) { v1 = p;  i1 = e; }
        }
        float s = v0 + v1 + 1e-6f;
        g_sel[2*t] = i0; g_sel[2*t+1] = i1;
        g_wt [2*t] = v0 / s; g_wt [2*t+1] = v1 / s;
    }
}

// ---------------- 2) Ordered capacity ranking ----------------
__global__ void rank_kernel() {
    const int e = blockIdx.x, tid = threadIdx.x;
    const int ITEMS = (T_TOK * TOPK) / 256;
    const int base = tid * ITEMS;
    int cnt = 0;
    for (int i = 0; i < ITEMS; i++) cnt += (g_sel[base + i] == e);
    __shared__ int s[256];
    s[tid] = cnt;
    __syncthreads();
    int off = 0, tot = 0;
    for (int j = 0; j < 256; j++) { int v = s[j]; tot += v; if (j < tid) off += v; }
    int r = off;
    for (int i = 0; i < ITEMS; i++) {
        int idx = base + i;
        if (g_sel[idx] == e) {
            if (r < CAP) { g_slot[idx] = e * CAP + r; g_src[e * CAP + r] = idx; }
            else g_slot[idx] = -1;
            r++;
        }
    }
    int filled = tot < CAP ? tot : CAP;
    if (tid == 0) g_filled[e] = filled;
    for (int r2 = filled + tid; r2 < CAP; r2 += 256) g_src[e * CAP + r2] = -1;
}

// ---------------- 3) Fused prep: convert x->fp16 (token-indexed) + transpose/convert W1,W2 ----------------
#define NT1 32768   // (DFF/32)*(DM/32)*NE
__global__ void prep_kernel(const float* __restrict__ x,
                            const float* __restrict__ w1,
                            const float* __restrict__ w2) {
    const int tx = threadIdx.x, ty = threadIdx.y;
    const int tid = ty * 32 + tx;
    int b = blockIdx.x;

    if (b < T_TOK) {                    // ---- straight convert of token row ----
        const float2* s = (const float2*)(x + (size_t)b * DM);
        __half2* dst = (__half2*)(g_Xt + (size_t)b * DM);
#pragma unroll
        for (int i = 0; i < 2; i++) {
            float2 v = s[tid + 256 * i];
            dst[tid + 256 * i] = __halves2half2(__float2half_rn(v.x), __float2half_rn(v.y));
        }
        return;
    }
    b -= T_TOK;
    const int wsel = b >> 15;           // 0: W1, 1: W2
    const int r = b & (NT1 - 1);
    const int R = wsel ? DFF : DM;
    const int C = wsel ? DM : DFF;
    const float* s = (wsel ? w2 : w1);
    __half* dst = (wsel ? g_W2h : g_W1h);
    const int ctiles = C / 32;
    const int cx = r % ctiles;
    const int ry = (r / ctiles) % (R / 32);
    const int e  = r / (ctiles * (R / 32));
    const int c0 = cx * 32, r0 = ry * 32;
    s   += (size_t)e * R * C;
    dst += (size_t)e * R * C;

    __shared__ float t[32][33];
#pragma unroll
    for (int i = 0; i < 4; i++)
        t[ty + 8*i][tx] = s[(size_t)(r0 + ty + 8*i) * C + c0 + tx];
    __syncthreads();
#pragma unroll
    for (int it = 0; it < 2; it++) {
        const int idx = tid + 256 * it;
        const int oc_l = idx >> 4;
        const int p    = idx & 15;
        float v0 = t[2*p][oc_l], v1 = t[2*p + 1][oc_l];
        size_t o = (size_t)(c0 + oc_l) * R + r0 + 2 * p;
        *(__half2*)(dst + o) = __halves2half2(__float2half_rn(v0), __float2half_rn(v1));
    }
}

// ---------------- 4/5) single-pass fp16 HMMA GEMM ----------------
// CTA tile 128x128, K-chunk 32, 256 thr, warps 4(M)x2(N), warp tile 32x64.
// 64B rows + XOR swizzle -> conflict-free, tile 8KB; 6-stage ring,
// ONE barrier per chunk-pair; fine-grained LDSM/MMA interleave.
// PHASE 0: A rows gathered from token-indexed g_Xt via g_src (fused gather).
// 2 CTAs/SM (96KB each). Padding M-tiles early-exit.
#define TILE_SM  (128 * 64)           // 8192 B
#define STAGE_SM (2 * TILE_SM)        // 16384 B
#define NSTAGE   6
#define SMEMD    (NSTAGE * STAGE_SM)  // 98304 B

template <int KD, int ND, int PHASE>
__global__ __launch_bounds__(256, 2) void mma_gemm_kernel() {
    const int e  = blockIdx.z;
    const int m0 = blockIdx.y * 128;
    if (m0 >= g_filled[e]) return;     // padding tile: outputs never read

    extern __shared__ __align__(128) char dsm[];
    const uint32_t smem0 = smem_u32(dsm);

    const int n0 = blockIdx.x * 128;
    const int tid = threadIdx.x;
    const int lane = tid & 31, wid = tid >> 5;
    const int wm = wid & 3, wn = wid >> 2;     // warp -> (row 32*wm, col 64*wn)

    const char* B = (const char*)((PHASE == 0 ? g_W1h : g_W2h) + ((size_t)e * ND + n0) * KD);

    float acc[2][8][4];
#pragma unroll
    for (int a = 0; a < 2; a++)
#pragma unroll
        for (int b = 0; b < 8; b++)
#pragma unroll
            for (int q = 0; q < 4; q++) acc[a][b][q] = 0.f;

    // ---- loader: rolling pointers, +64B per chunk ----
    const int lrow0 = tid >> 2, lseg = tid & 3;
    const uint32_t swzseg = (uint32_t)(lseg ^ ((lrow0 >> 1) & 3)) * 16;
    const uint32_t dA0 = lrow0 * 64 + swzseg;

    const char* pA0;
    const char* pA1;
    if (PHASE == 0) {
        // fused gather: per-row token pointers into g_Xt
        const int s0 = g_src[e * CAP + m0 + lrow0];
        const int s1 = g_src[e * CAP + m0 + lrow0 + 64];
        const int t0 = s0 < 0 ? 0 : (s0 >> 1);
        const int t1 = s1 < 0 ? 0 : (s1 >> 1);
        pA0 = (const char*)(g_Xt + (size_t)t0 * DM) + lseg * 16;
        pA1 = (const char*)(g_Xt + (size_t)t1 * DM) + lseg * 16;
    } else {
        const char* A = (const char*)(g_Hh + ((size_t)e * CAP + m0) * KD);
        pA0 = A + (size_t)lrow0 * (KD * 2) + lseg * 16;
        pA1 = pA0 + (size_t)64 * (KD * 2);
    }
    const char* pB0 = B + (size_t)lrow0 * (KD * 2) + lseg * 16;
    const char* pB1 = pB0 + (size_t)64 * (KD * 2);

    auto load_next = [&](int slot) {
        const uint32_t buf = smem0 + slot * STAGE_SM;
        cp16(buf + dA0,                   pA0);
        cp16(buf + dA0 + 64 * 64,         pA1);
        cp16(buf + TILE_SM + dA0,         pB0);
        cp16(buf + TILE_SM + dA0 + 64*64, pB1);
        CP_COMMIT();
        pA0 += 64; pA1 += 64; pB0 += 64; pB1 += 64;
    };

    const int NC = KD / 32;
    load_next(0); load_next(1); load_next(2); load_next(3);

    // ---- ldmatrix addressing (swizzled) ----
    const int lrow = lane & 15;
    const int hi   = (lane >> 4) & 1;
    const uint32_t swz = ((uint32_t)lrow >> 1) & 3;
    uint32_t offA[2], offB[4];
#pragma unroll
    for (int mt = 0; mt < 2; mt++) offA[mt] = (wm * 32 + mt * 16 + lrow) * 64;
#pragma unroll
    for (int g = 0; g < 4; g++)    offB[g] = (wn * 64 + g * 16 + lrow) * 64;
    uint32_t cb[2];
#pragma unroll
    for (int kk = 0; kk < 2; kk++) cb[kk] = (uint32_t)((2 * kk + hi) ^ swz) * 16;

    // fine-grained LDSM/MMA interleave (R14-proven)
    auto compute_chunk = [&](int slot) {
        const uint32_t sA = smem0 + slot * STAGE_SM;
        const uint32_t sB = sA + TILE_SM;
#pragma unroll
        for (int kk = 0; kk < 2; kk++) {
            uint32_t ah[2][4], bh0[4], bh1[4], bh2[4], bh3[4];
            ldsm4(bh0, sB + offB[0] + cb[kk]);
            ldsm4(bh1, sB + offB[1] + cb[kk]);
            ldsm4(ah[0], sA + offA[0] + cb[kk]);
            ldsm4(ah[1], sA + offA[1] + cb[kk]);
            mma16816(acc[0][0], ah[0], bh0[0], bh0[2]);
            mma16816(acc[0][1], ah[0], bh0[1], bh0[3]);
            ldsm4(bh2, sB + offB[2] + cb[kk]);
            mma16816(acc[1][0], ah[1], bh0[0], bh0[2]);
            mma16816(acc[1][1], ah[1], bh0[1], bh0[3]);
            ldsm4(bh3, sB + offB[3] + cb[kk]);
            mma16816(acc[0][2], ah[0], bh1[0], bh1[2]);
            mma16816(acc[0][3], ah[0], bh1[1], bh1[3]);
            mma16816(acc[1][2], ah[1], bh1[0], bh1[2]);
            mma16816(acc[1][3], ah[1], bh1[1], bh1[3]);
            mma16816(acc[0][4], ah[0], bh2[0], bh2[2]);
            mma16816(acc[0][5], ah[0], bh2[1], bh2[3]);
            mma16816(acc[1][4], ah[1], bh2[0], bh2[2]);
            mma16816(acc[1][5], ah[1], bh2[1], bh2[3]);
            mma16816(acc[0][6], ah[0], bh3[0], bh3[2]);
            mma16816(acc[0][7], ah[0], bh3[1], bh3[3]);
            mma16816(acc[1][6], ah[1], bh3[0], bh3[2]);
            mma16816(acc[1][7], ah[1], bh3[1], bh3[3]);
        }
    };

    int sc = 0;       // slot of chunk p
    int sl = 4;       // slot of next chunk to load
    for (int p = 0; p < NC; p += 2) {
        if (p < NC - 2) cp_wait<2>(); else cp_wait<0>();
        __syncthreads();

        compute_chunk(sc);
        if (p + 4 < NC) load_next(sl);
        int sl2 = (sl + 1 == NSTAGE) ? 0 : sl + 1;
        if (p + 5 < NC) load_next(sl2);
        sl = (sl2 + 1 == NSTAGE) ? 0 : sl2 + 1;

        int sc2 = (sc + 1 == NSTAGE) ? 0 : sc + 1;
        compute_chunk(sc2);
        sc = (sc2 + 1 == NSTAGE) ? 0 : sc2 + 1;
    }

    // -------- epilogue (fp16 out; gelu on phase 0) --------
#pragma unroll
    for (int mt = 0; mt < 2; mt++) {
#pragma unroll
        for (int h = 0; h < 2; h++) {
            const int row = m0 + wm * 32 + mt * 16 + (lane >> 2) + 8 * h;
            const int colb = n0 + wn * 64 + 2 * (lane & 3);
            __half2* hp = (__half2*)((PHASE == 0 ? g_Hh : g_Yh) + ((size_t)e * CAP + row) * ND + colb);
#pragma unroll
            for (int nt = 0; nt < 8; nt++) {
                float v0 = acc[mt][nt][2*h];
                float v1 = acc[mt][nt][2*h + 1];
                if (PHASE == 0) { v0 = gelu_f(v0); v1 = gelu_f(v1); }
                hp[nt * 4] = __halves2half2(__float2half_rn(v0), __float2half_rn(v1));
            }
        }
    }
}

// ---------------- 6) Combine ----------------
__global__ void combine_kernel(float* __restrict__ out) {
    const int t = blockIdx.x;
    const int s0 = g_slot[2*t], s1 = g_slot[2*t+1];
    const float w0 = g_wt[2*t], w1 = g_wt[2*t+1];
    const __half2* Y2 = (const __half2*)g_Yh;
    float2* o = ((float2*)out) + (size_t)t * (DM / 2);
    for (int i = threadIdx.x; i < DM / 2; i += blockDim.x) {
        float2 r = make_float2(0.f, 0.f);
        if (s0 >= 0) {
            float2 y = __half22float2(Y2[(size_t)s0 * (DM/2) + i]);
            r.x += w0 * y.x; r.y += w0 * y.y;
        }
        if (s1 >= 0) {
            float2 y = __half22float2(Y2[(size_t)s1 * (DM/2) + i]);
            r.x += w1 * y.x; r.y += w1 * y.y;
        }
        o[i] = r;
    }
}

// ---------------- Launch ----------------
extern "C" void kernel_launch(void* const* d_in, const int* in_sizes, int n_in,
                              void* d_out, int out_size) {
    (void)in_sizes; (void)n_in; (void)out_size;
    const float* x  = (const float*)d_in[0];
    const float* gw = (const float*)d_in[1];
    const float* w1 = (const float*)d_in[2];   // [16,1024,2048]
    const float* w2 = (const float*)d_in[3];   // [16,2048,1024]
    float* out = (float*)d_out;

    cudaFuncSetAttribute(mma_gemm_kernel<DM,  DFF, 0>, cudaFuncAttributeMaxDynamicSharedMemorySize, SMEMD);
    cudaFuncSetAttribute(mma_gemm_kernel<DFF, DM,  1>, cudaFuncAttributeMaxDynamicSharedMemorySize, SMEMD);

    gate_kernel<<<T_TOK / 8, 256>>>(x, gw);
    rank_kernel<<<NE, 256>>>();
    prep_kernel<<<T_TOK + 2 * NT1, dim3(32, 8)>>>(x, w1, w2);
    mma_gemm_kernel<DM,  DFF, 0><<<dim3(DFF/128, CAP/128, NE), 256, SMEMD>>>();
    mma_gemm_kernel<DFF, DM,  1><<<dim3(DM/128,  CAP/128, NE), 256, SMEMD>>>();
    combine_kernel<<<T_TOK, 256>>>(out);
}